// round 2
// baseline (speedup 1.0000x reference)
#include <cuda_runtime.h>

// Scratch: __device__ globals (no allocation allowed).
#define NMAX 1000000
__device__ int   g_deg[NMAX];
__device__ float g_dinv[NMAX];
__device__ float g_s1[NMAX];
__device__ float g_y[NMAX];

// Pass 0: deg = 1 (self-loop)
__global__ void k_init(int n) {
    int i = blockIdx.x * blockDim.x + threadIdx.x;
    if (i < n) g_deg[i] = 1;
}

// Pass 1: count incoming edges at dst
__global__ void k_deg(const int* __restrict__ dst, int E) {
    int i = blockIdx.x * blockDim.x + threadIdx.x;
    if (i < E) atomicAdd(&g_deg[dst[i]], 1);
}

// Pass 2: dinv = rsqrt(deg); seed s1 with self-loop term dinv^2 * x
__global__ void k_dinv(const float* __restrict__ x, int n) {
    int i = blockIdx.x * blockDim.x + threadIdx.x;
    if (i < n) {
        float di = rsqrtf((float)g_deg[i]);   // deg >= 1 always (self-loop)
        g_dinv[i] = di;
        g_s1[i] = di * di * x[i];
    }
}

// Pass 3: scalar scatter  s1[dst] += dinv[src]*dinv[dst]*x[src]
__global__ void k_edge1(const int* __restrict__ src,
                        const int* __restrict__ dst,
                        const float* __restrict__ x, int E) {
    int i = blockIdx.x * blockDim.x + threadIdx.x;
    if (i < E) {
        int s = src[i];
        int d = dst[i];
        float v = g_dinv[s] * g_dinv[d] * __ldg(&x[s]);
        atomicAdd(&g_s1[d], v);
    }
}

// Pass 4: per-node 8-wide MLP: y = sum_k relu(s1*W1[k]+b1[k])*W2[k]
//         also seed out with self-loop term + b2
__global__ void k_node(const float* __restrict__ W1, const float* __restrict__ b1,
                       const float* __restrict__ W2, const float* __restrict__ b2,
                       float* __restrict__ out, int n) {
    int i = blockIdx.x * blockDim.x + threadIdx.x;
    if (i < n) {
        float s = g_s1[i];
        float acc = 0.0f;
#pragma unroll
        for (int k = 0; k < 8; k++) {
            float h = fmaf(s, __ldg(&W1[k]), __ldg(&b1[k]));
            h = fmaxf(h, 0.0f);
            acc = fmaf(h, __ldg(&W2[k]), acc);
        }
        g_y[i] = acc;
        float di = g_dinv[i];
        out[i] = di * di * acc + __ldg(&b2[0]);
    }
}

// Pass 5: scalar scatter  out[dst] += dinv[src]*dinv[dst]*y[src]
__global__ void k_edge2(const int* __restrict__ src,
                        const int* __restrict__ dst,
                        float* __restrict__ out, int E) {
    int i = blockIdx.x * blockDim.x + threadIdx.x;
    if (i < E) {
        int s = src[i];
        int d = dst[i];
        float v = g_dinv[s] * g_dinv[d] * g_y[s];
        atomicAdd(&out[d], v);
    }
}

extern "C" void kernel_launch(void* const* d_in, const int* in_sizes, int n_in,
                              void* d_out, int out_size) {
    const float* x  = (const float*)d_in[0];
    const int*   ei = (const int*)d_in[1];     // [2, E] (int64 canonicalized to int32)
    const float* W1 = (const float*)d_in[2];   // [1,8]
    const float* b1 = (const float*)d_in[3];   // [8]
    const float* W2 = (const float*)d_in[4];   // [8,1]
    const float* b2 = (const float*)d_in[5];   // [1]
    float* out = (float*)d_out;

    int n = in_sizes[0];           // 1,000,000
    int E = in_sizes[1] / 2;       // 10,000,000
    const int* src = ei;
    const int* dst = ei + E;

    const int T = 256;
    int gn = (n + T - 1) / T;
    int gE = (E + T - 1) / T;

    k_init <<<gn, T>>>(n);
    k_deg  <<<gE, T>>>(dst, E);
    k_dinv <<<gn, T>>>(x, n);
    k_edge1<<<gE, T>>>(src, dst, x, E);
    k_node <<<gn, T>>>(W1, b1, W2, b2, out, n);
    k_edge2<<<gE, T>>>(src, dst, out, E);
}

// round 3
// speedup vs baseline: 1.5159x; 1.5159x over previous
#include <cuda_runtime.h>

// Scratch: __device__ globals (no allocation allowed).
#define NMAX 1000000
__device__ int   g_deg[NMAX];
__device__ float g_dinv[NMAX];
__device__ float g_xd[NMAX];   // dinv * x
__device__ float g_a1[NMAX];   // raw layer-1 accumulator (seeded with xd)
__device__ float g_yd[NMAX];   // dinv * y
__device__ float g_a2[NMAX];   // raw layer-2 accumulator (seeded with yd)

// Pass 0: deg = 1 (self-loop)
__global__ void k_init(int n) {
    int i = blockIdx.x * blockDim.x + threadIdx.x;
    if (i < n) g_deg[i] = 1;
}

// Pass 1: count incoming edges at dst
__global__ void k_deg(const int* __restrict__ dst, int E) {
    int i = blockIdx.x * blockDim.x + threadIdx.x;
    if (i < E) atomicAdd(&g_deg[dst[i]], 1);
}

// Pass 2: dinv = rsqrt(deg); xd = dinv*x; seed a1 = xd (self-loop term)
__global__ void k_prep(const float* __restrict__ x, int n) {
    int i = blockIdx.x * blockDim.x + threadIdx.x;
    if (i < n) {
        float di = rsqrtf((float)g_deg[i]);   // deg >= 1 always
        g_dinv[i] = di;
        float xd = di * x[i];
        g_xd[i] = xd;
        g_a1[i] = xd;
    }
}

// Pass 3: raw scatter  a1[dst] += xd[src]   (1 gather + 1 atomic per edge)
__global__ void k_edge1(const int* __restrict__ src,
                        const int* __restrict__ dst, int E) {
    int i = blockIdx.x * blockDim.x + threadIdx.x;
    if (i < E) {
        atomicAdd(&g_a1[dst[i]], __ldg(&g_xd[src[i]]));
    }
}

// Pass 4: s1 = dinv*a1; MLP -> y; yd = dinv*y; seed a2 = yd
__global__ void k_node(const float* __restrict__ W1, const float* __restrict__ b1,
                       const float* __restrict__ W2, int n) {
    int i = blockIdx.x * blockDim.x + threadIdx.x;
    if (i < n) {
        float di = g_dinv[i];
        float s = di * g_a1[i];
        float acc = 0.0f;
#pragma unroll
        for (int k = 0; k < 8; k++) {
            float h = fmaf(s, __ldg(&W1[k]), __ldg(&b1[k]));
            h = fmaxf(h, 0.0f);
            acc = fmaf(h, __ldg(&W2[k]), acc);
        }
        float yd = di * acc;
        g_yd[i] = yd;
        g_a2[i] = yd;
    }
}

// Pass 5: raw scatter  a2[dst] += yd[src]
__global__ void k_edge2(const int* __restrict__ src,
                        const int* __restrict__ dst, int E) {
    int i = blockIdx.x * blockDim.x + threadIdx.x;
    if (i < E) {
        atomicAdd(&g_a2[dst[i]], __ldg(&g_yd[src[i]]));
    }
}

// Pass 6: out = dinv*a2 + b2
__global__ void k_final(const float* __restrict__ b2, float* __restrict__ out, int n) {
    int i = blockIdx.x * blockDim.x + threadIdx.x;
    if (i < n) {
        out[i] = g_dinv[i] * g_a2[i] + __ldg(&b2[0]);
    }
}

extern "C" void kernel_launch(void* const* d_in, const int* in_sizes, int n_in,
                              void* d_out, int out_size) {
    const float* x  = (const float*)d_in[0];
    const int*   ei = (const int*)d_in[1];     // [2, E]
    const float* W1 = (const float*)d_in[2];   // [1,8]
    const float* b1 = (const float*)d_in[3];   // [8]
    const float* W2 = (const float*)d_in[4];   // [8,1]
    const float* b2 = (const float*)d_in[5];   // [1]
    float* out = (float*)d_out;

    int n = in_sizes[0];           // 1,000,000
    int E = in_sizes[1] / 2;       // 10,000,000
    const int* src = ei;
    const int* dst = ei + E;

    const int T = 256;
    int gn = (n + T - 1) / T;
    int gE = (E + T - 1) / T;

    k_init <<<gn, T>>>(n);
    k_deg  <<<gE, T>>>(dst, E);
    k_prep <<<gn, T>>>(x, n);
    k_edge1<<<gE, T>>>(src, dst, E);
    k_node <<<gn, T>>>(W1, b1, W2, n);
    k_edge2<<<gE, T>>>(src, dst, E);
    k_final<<<gn, T>>>(b2, out, n);
}

// round 4
// speedup vs baseline: 1.5740x; 1.0383x over previous
#include <cuda_runtime.h>
#include <cstdint>

// Scratch: __device__ globals (no allocation allowed).
#define NMAX 1000000
__device__ int   g_deg[NMAX];   // starts 0; each execution returns it to 0
__device__ float g_dinv[NMAX];
__device__ float g_xd[NMAX];    // dinv * x
__device__ float g_a1[NMAX];    // raw layer-1 accumulator (seeded with xd)
__device__ float g_yd[NMAX];    // dinv * y
__device__ float g_a2[NMAX];    // raw layer-2 accumulator (seeded with yd)

// ---------------------------------------------------------------------------
// Pass 1: count incoming edges at dst (deg starts at 0; self-loop added later)
__global__ void k_deg_v4(const int* __restrict__ dst, int E) {
    int i = blockIdx.x * blockDim.x + threadIdx.x;
    int base = i * 4;
    if (base + 3 < E) {
        int4 d = __ldcs((const int4*)(dst + base));
        atomicAdd(&g_deg[d.x], 1);
        atomicAdd(&g_deg[d.y], 1);
        atomicAdd(&g_deg[d.z], 1);
        atomicAdd(&g_deg[d.w], 1);
    } else {
        for (int j = base; j < E; j++) atomicAdd(&g_deg[__ldcs(&dst[j])], 1);
    }
}
__global__ void k_deg_s(const int* __restrict__ dst, int E) {
    int i = blockIdx.x * blockDim.x + threadIdx.x;
    if (i < E) atomicAdd(&g_deg[dst[i]], 1);
}

// ---------------------------------------------------------------------------
// Pass 2: dinv = rsqrt(deg+1); xd = dinv*x; seed a1 = xd; reset deg = 0
__global__ void k_prep_v4(const float* __restrict__ x, int n) {
    int i = blockIdx.x * blockDim.x + threadIdx.x;
    int base = i * 4;
    if (base + 3 < n) {
        int4   dg = *(const int4*)(g_deg + base);
        float4 xv = __ldcs((const float4*)(x + base));
        float4 di, xd;
        di.x = rsqrtf((float)(dg.x + 1)); di.y = rsqrtf((float)(dg.y + 1));
        di.z = rsqrtf((float)(dg.z + 1)); di.w = rsqrtf((float)(dg.w + 1));
        xd.x = di.x * xv.x; xd.y = di.y * xv.y; xd.z = di.z * xv.z; xd.w = di.w * xv.w;
        *(float4*)(g_dinv + base) = di;
        *(float4*)(g_xd  + base) = xd;
        *(float4*)(g_a1  + base) = xd;
        *(int4*)(g_deg + base) = make_int4(0, 0, 0, 0);
    } else {
        for (int j = base; j < n; j++) {
            float di = rsqrtf((float)(g_deg[j] + 1));
            g_dinv[j] = di;
            float xd = di * x[j];
            g_xd[j] = xd;
            g_a1[j] = xd;
            g_deg[j] = 0;
        }
    }
}

// ---------------------------------------------------------------------------
// Pass 3: raw scatter  a1[dst] += xd[src]
__global__ void k_edge1_v4(const int* __restrict__ src,
                           const int* __restrict__ dst, int E) {
    int i = blockIdx.x * blockDim.x + threadIdx.x;
    int base = i * 4;
    if (base + 3 < E) {
        int4 s = __ldcs((const int4*)(src + base));
        int4 d = __ldcs((const int4*)(dst + base));
        float v0 = __ldg(&g_xd[s.x]);
        float v1 = __ldg(&g_xd[s.y]);
        float v2 = __ldg(&g_xd[s.z]);
        float v3 = __ldg(&g_xd[s.w]);
        atomicAdd(&g_a1[d.x], v0);
        atomicAdd(&g_a1[d.y], v1);
        atomicAdd(&g_a1[d.z], v2);
        atomicAdd(&g_a1[d.w], v3);
    } else {
        for (int j = base; j < E; j++)
            atomicAdd(&g_a1[dst[j]], __ldg(&g_xd[src[j]]));
    }
}
__global__ void k_edge1_s(const int* __restrict__ src,
                          const int* __restrict__ dst, int E) {
    int i = blockIdx.x * blockDim.x + threadIdx.x;
    if (i < E) atomicAdd(&g_a1[dst[i]], __ldg(&g_xd[src[i]]));
}

// ---------------------------------------------------------------------------
// Pass 4: s1 = dinv*a1; MLP -> y; yd = dinv*y; seed a2 = yd
__device__ __forceinline__ float mlp8(float s, const float* W1, const float* b1,
                                      const float* W2) {
    float acc = 0.0f;
#pragma unroll
    for (int k = 0; k < 8; k++) {
        float h = fmaf(s, __ldg(&W1[k]), __ldg(&b1[k]));
        h = fmaxf(h, 0.0f);
        acc = fmaf(h, __ldg(&W2[k]), acc);
    }
    return acc;
}

__global__ void k_node_v4(const float* __restrict__ W1, const float* __restrict__ b1,
                          const float* __restrict__ W2, int n) {
    int i = blockIdx.x * blockDim.x + threadIdx.x;
    int base = i * 4;
    if (base + 3 < n) {
        float4 di = *(const float4*)(g_dinv + base);
        float4 a  = *(const float4*)(g_a1 + base);
        float4 yd;
        yd.x = di.x * mlp8(di.x * a.x, W1, b1, W2);
        yd.y = di.y * mlp8(di.y * a.y, W1, b1, W2);
        yd.z = di.z * mlp8(di.z * a.z, W1, b1, W2);
        yd.w = di.w * mlp8(di.w * a.w, W1, b1, W2);
        *(float4*)(g_yd + base) = yd;
        *(float4*)(g_a2 + base) = yd;
    } else {
        for (int j = base; j < n; j++) {
            float di = g_dinv[j];
            float yd = di * mlp8(di * g_a1[j], W1, b1, W2);
            g_yd[j] = yd;
            g_a2[j] = yd;
        }
    }
}

// ---------------------------------------------------------------------------
// Pass 5: raw scatter  a2[dst] += yd[src]
__global__ void k_edge2_v4(const int* __restrict__ src,
                           const int* __restrict__ dst, int E) {
    int i = blockIdx.x * blockDim.x + threadIdx.x;
    int base = i * 4;
    if (base + 3 < E) {
        int4 s = __ldcs((const int4*)(src + base));
        int4 d = __ldcs((const int4*)(dst + base));
        float v0 = __ldg(&g_yd[s.x]);
        float v1 = __ldg(&g_yd[s.y]);
        float v2 = __ldg(&g_yd[s.z]);
        float v3 = __ldg(&g_yd[s.w]);
        atomicAdd(&g_a2[d.x], v0);
        atomicAdd(&g_a2[d.y], v1);
        atomicAdd(&g_a2[d.z], v2);
        atomicAdd(&g_a2[d.w], v3);
    } else {
        for (int j = base; j < E; j++)
            atomicAdd(&g_a2[dst[j]], __ldg(&g_yd[src[j]]));
    }
}
__global__ void k_edge2_s(const int* __restrict__ src,
                          const int* __restrict__ dst, int E) {
    int i = blockIdx.x * blockDim.x + threadIdx.x;
    if (i < E) atomicAdd(&g_a2[dst[i]], __ldg(&g_yd[src[i]]));
}

// ---------------------------------------------------------------------------
// Pass 6: out = dinv*a2 + b2
__global__ void k_final_v4(const float* __restrict__ b2, float* __restrict__ out, int n) {
    int i = blockIdx.x * blockDim.x + threadIdx.x;
    int base = i * 4;
    float bb = __ldg(&b2[0]);
    if (base + 3 < n) {
        float4 di = *(const float4*)(g_dinv + base);
        float4 a  = *(const float4*)(g_a2 + base);
        float4 o;
        o.x = fmaf(di.x, a.x, bb);
        o.y = fmaf(di.y, a.y, bb);
        o.z = fmaf(di.z, a.z, bb);
        o.w = fmaf(di.w, a.w, bb);
        *(float4*)(out + base) = o;
    } else {
        for (int j = base; j < n; j++) out[j] = fmaf(g_dinv[j], g_a2[j], bb);
    }
}

extern "C" void kernel_launch(void* const* d_in, const int* in_sizes, int n_in,
                              void* d_out, int out_size) {
    const float* x  = (const float*)d_in[0];
    const int*   ei = (const int*)d_in[1];     // [2, E]
    const float* W1 = (const float*)d_in[2];
    const float* b1 = (const float*)d_in[3];
    const float* W2 = (const float*)d_in[4];
    const float* b2 = (const float*)d_in[5];
    float* out = (float*)d_out;

    int n = in_sizes[0];           // 1,000,000
    int E = in_sizes[1] / 2;       // 10,000,000
    const int* src = ei;
    const int* dst = ei + E;

    const int T = 256;
    int gn4 = ((n + 3) / 4 + T - 1) / T;
    int gE4 = ((E + 3) / 4 + T - 1) / T;
    int gE  = (E + T - 1) / T;

    // int4 paths need 16B-aligned dst (= ei + E); holds when E % 4 == 0.
    bool v4ok = ((E & 3) == 0) && ((((uintptr_t)ei) & 15) == 0);

    if (v4ok) {
        k_deg_v4  <<<gE4, T>>>(dst, E);
        k_prep_v4 <<<gn4, T>>>(x, n);
        k_edge1_v4<<<gE4, T>>>(src, dst, E);
        k_node_v4 <<<gn4, T>>>(W1, b1, W2, n);
        k_edge2_v4<<<gE4, T>>>(src, dst, E);
        k_final_v4<<<gn4, T>>>(b2, out, n);
    } else {
        k_deg_s   <<<gE, T>>>(dst, E);
        k_prep_v4 <<<gn4, T>>>(x, n);   // n-side vec path self-checks bounds
        k_edge1_s <<<gE, T>>>(src, dst, E);
        k_node_v4 <<<gn4, T>>>(W1, b1, W2, n);
        k_edge2_s <<<gE, T>>>(src, dst, E);
        k_final_v4<<<gn4, T>>>(b2, out, n);
    }
}